// round 16
// baseline (speedup 1.0000x reference)
#include <cuda_runtime.h>
#include <cuda_fp16.h>
#include <cstdint>

#define CIN 16
#define COUT 32
#define K2 9
#define MAXN 2000000
#define WSTR 40    // weight SMEM row stride in halves (80 B)
#define A1B 48     // conv1 A-tile row stride bytes
#define AROW 80    // conv2 A-tile row stride bytes
#define M2 48      // conv2 warp tile rows

// fp16 intermediate h1 (128 MB ~ L2-resident) and fp16 copy of x (64 MB).
__device__ __align__(256) __half g_h1h[(size_t)MAXN * COUT];
__device__ __align__(256) __half g_xh[(size_t)MAXN * CIN];
// fused gather index written by conv1, consumed by conv2
__device__ int g_cidx[(size_t)K2 * MAXN];
// fp16 weights (compact)
__device__ __half g_w1h[K2 * CIN * COUT];
__device__ __half g_w2h[K2 * COUT * COUT];
__device__ __half g_wph[CIN * COUT];
// zero row (64 B) for masked / out-of-range gathers
__device__ __align__(64) unsigned g_zrow[16] = {};

// ---- PTX wrappers ----
__device__ __forceinline__ void ldg256(const void* p, uint4& a, uint4& b) {
    asm("ld.global.nc.v8.b32 {%0,%1,%2,%3,%4,%5,%6,%7}, [%8];"
        : "=r"(a.x), "=r"(a.y), "=r"(a.z), "=r"(a.w),
          "=r"(b.x), "=r"(b.y), "=r"(b.z), "=r"(b.w)
        : "l"(p));
}
__device__ __forceinline__ void ldsm4(unsigned r[4], unsigned addr) {
    asm volatile("ldmatrix.sync.aligned.m8n8.x4.shared.b16 {%0,%1,%2,%3}, [%4];"
                 : "=r"(r[0]), "=r"(r[1]), "=r"(r[2]), "=r"(r[3]) : "r"(addr));
}
__device__ __forceinline__ void ldsm4t(unsigned r[4], unsigned addr) {
    asm volatile("ldmatrix.sync.aligned.m8n8.x4.trans.shared.b16 {%0,%1,%2,%3}, [%4];"
                 : "=r"(r[0]), "=r"(r[1]), "=r"(r[2]), "=r"(r[3]) : "r"(addr));
}
__device__ __forceinline__ void mma16816(float c[4], const unsigned a[4],
                                         unsigned b0, unsigned b1) {
    asm("mma.sync.aligned.m16n8k16.row.col.f32.f16.f16.f32 "
        "{%0,%1,%2,%3}, {%4,%5,%6,%7}, {%8,%9}, {%0,%1,%2,%3};"
        : "+f"(c[0]), "+f"(c[1]), "+f"(c[2]), "+f"(c[3])
        : "r"(a[0]), "r"(a[1]), "r"(a[2]), "r"(a[3]), "r"(b0), "r"(b1));
}
__device__ __forceinline__ int sel_idx(int ix, unsigned mk) {
    int r;
    asm("{ .reg .pred p; setp.ne.u32 p, %1, 0; selp.b32 %0, %2, -1, p; }"
        : "=r"(r) : "r"(mk), "r"(ix));
    return r;
}

// =====================================================================
// merged prologue: x -> fp16 copy  +  weights -> fp16
// =====================================================================
__global__ __launch_bounds__(256)
void xhw_kernel(const float* __restrict__ x,
                const float* __restrict__ W1, const float* __restrict__ W2,
                const float* __restrict__ Wp, int n) {
    int gid = blockIdx.x * blockDim.x + threadIdx.x;
    int stride = gridDim.x * blockDim.x;
    int total8 = n * CIN / 8;
    const float4* x4 = (const float4*)x;
    uint4* o4 = (uint4*)g_xh;
    for (int j = gid; j < total8; j += stride) {
        float4 a = __ldg(x4 + 2 * j), b = __ldg(x4 + 2 * j + 1);
        uint4 o; __half2 h;
        h = __floats2half2_rn(a.x, a.y); o.x = *(unsigned*)&h;
        h = __floats2half2_rn(a.z, a.w); o.y = *(unsigned*)&h;
        h = __floats2half2_rn(b.x, b.y); o.z = *(unsigned*)&h;
        h = __floats2half2_rn(b.z, b.w); o.w = *(unsigned*)&h;
        o4[j] = o;
    }
    if (gid < K2 * COUT * COUT) {
        if (gid < K2 * CIN * COUT) g_w1h[gid] = __float2half(W1[gid]);
        g_w2h[gid] = __float2half(W2[gid]);
        if (gid < CIN * COUT) g_wph[gid] = __float2half(Wp[gid]);
    }
}

// =====================================================================
// conv1: h1(fp16) = relu( sum_k x_h[idx] @ W1[k] + b1 )
// warp tile M=64, rows depth-2, idx prefetched further; ALSO writes cidx.
// =====================================================================
__global__ __launch_bounds__(256, 2)
void conv1_kernel(const int* __restrict__ nbr_idx,
                  const unsigned* __restrict__ nbr_mask,
                  const float* __restrict__ b1, int n) {
    __shared__ __half wsm[K2 * CIN * WSTR];                     // 11.5 KB
    __shared__ float bsm[COUT];
    __shared__ __align__(16) __half atile[8 * 64 * (A1B / 2)];  // 24 KB

    const int t = threadIdx.x, lane = t & 31, w = t >> 5;
    for (int i = t; i < K2 * CIN * COUT; i += 256) {
        int row = i >> 5, cc = i & 31;
        wsm[row * WSTR + cc] = g_w1h[i];
    }
    if (t < COUT) bsm[t] = __ldg(b1 + t);
    __syncthreads();

    const int grp = lane >> 2, tig = lane & 3;
    const int sub = lane & 7, ti = lane >> 3;
    const int v0w = blockIdx.x * 512 + w * 64;
    const int vA = v0w + lane, vB = vA + 32;

    char* arowA = (char*)atile + w * 64 * A1B + lane * A1B;
    char* arowB = arowA + 32 * A1B;
    const unsigned abase =
        (unsigned)__cvta_generic_to_shared((char*)atile + w * 64 * A1B);
    const unsigned wb0 = (unsigned)__cvta_generic_to_shared(wsm);
    const int lro = sub + ((ti & 1) << 3);
    const int lco = (ti >> 1) << 4;

    float acc[4][4][4];
#pragma unroll
    for (int m = 0; m < 4; m++)
#pragma unroll
        for (int nt = 0; nt < 4; nt++) {
            float c0 = bsm[8 * nt + 2 * tig], c1 = bsm[8 * nt + 2 * tig + 1];
            acc[m][nt][0] = c0; acc[m][nt][1] = c1;
            acc[m][nt][2] = c0; acc[m][nt][3] = c1;
        }

    // loads idx+mask, folds, AND persists cidx for conv2 (coalesced STG.32)
    auto load_idx = [&](int k) -> int2 {
        int2 r; r.x = -1; r.y = -1;
        if (vA < n) {
            int ix = __ldg(nbr_idx + (size_t)k * n + vA);
            unsigned mk = __ldg(nbr_mask + (size_t)k * n + vA);
            r.x = sel_idx(ix, mk);
            g_cidx[(size_t)k * n + vA] = r.x;
        }
        if (vB < n) {
            int ix = __ldg(nbr_idx + (size_t)k * n + vB);
            unsigned mk = __ldg(nbr_mask + (size_t)k * n + vB);
            r.y = sel_idx(ix, mk);
            g_cidx[(size_t)k * n + vB] = r.y;
        }
        return r;
    };

    uint4 gA[2][2], gB[2][2];
    auto load_rows = [&](int2 ci, int buf) {
        const void* pA = (ci.x >= 0) ? (const void*)(g_xh + (size_t)ci.x * CIN)
                                     : (const void*)g_zrow;
        const void* pB = (ci.y >= 0) ? (const void*)(g_xh + (size_t)ci.y * CIN)
                                     : (const void*)g_zrow;
        ldg256(pA, gA[buf][0], gA[buf][1]);
        ldg256(pB, gB[buf][0], gB[buf][1]);
    };

    load_rows(load_idx(0), 0);
    load_rows(load_idx(1), 1);
    int2 inext = load_idx(2);

#pragma unroll
    for (int k = 0; k < K2; k++) {
        int cur = k & 1;
        ((uint4*)arowA)[0] = gA[cur][0];
        ((uint4*)arowA)[1] = gA[cur][1];
        ((uint4*)arowB)[0] = gB[cur][0];
        ((uint4*)arowB)[1] = gB[cur][1];
        __syncwarp();
        if (k + 2 < K2) load_rows(inext, cur);
        if (k + 3 < K2) inext = load_idx(k + 3);
        unsigned bw[8];
        unsigned wtap = wb0 + k * (CIN * WSTR * 2) + lro * (WSTR * 2) + lco;
        ldsm4t(bw,     wtap);
        ldsm4t(bw + 4, wtap + 32);
#pragma unroll
        for (int m = 0; m < 4; m++) {
            unsigned av[4];
            ldsm4(av, abase + (16 * m + lro) * A1B + lco);
            mma16816(acc[m][0], av, bw[0], bw[1]);
            mma16816(acc[m][1], av, bw[2], bw[3]);
            mma16816(acc[m][2], av, bw[4], bw[5]);
            mma16816(acc[m][3], av, bw[6], bw[7]);
        }
        __syncwarp();
    }

    // epilogue: relu -> fp16 h1
#pragma unroll
    for (int m = 0; m < 4; m++) {
        int vg0 = v0w + 16 * m + grp, vg1 = vg0 + 8;
#pragma unroll
        for (int nt = 0; nt < 4; nt++) {
            const float* a = acc[m][nt];
            if (vg0 < n) {
                __half2 h = __floats2half2_rn(fmaxf(a[0], 0.f), fmaxf(a[1], 0.f));
                *(__half2*)(g_h1h + (size_t)vg0 * COUT + 8 * nt + 2 * tig) = h;
            }
            if (vg1 < n) {
                __half2 h = __floats2half2_rn(fmaxf(a[2], 0.f), fmaxf(a[3], 0.f));
                *(__half2*)(g_h1h + (size_t)vg1 * COUT + 8 * nt + 2 * tig) = h;
            }
        }
    }
}

// =====================================================================
// conv2 + residual: warp tile M=48, 9 taps K=32, depth-2 register staging
// (2 sets x 24 regs) -> LDG slack ~2 taps. Pair-cooperative gathers.
// Reads single cidx stream produced by conv1.
// =====================================================================
__global__ __launch_bounds__(256, 2)
void conv2_kernel(const float* __restrict__ b2, const float* __restrict__ bp,
                  float* __restrict__ out, int n) {
    extern __shared__ char smem[];
    __half* atile = (__half*)smem;                          // 8 * 48 * 80 B = 30720
    __half* wsm   = (__half*)(smem + 8 * M2 * AROW);        // 9*32*WSTR
    __half* wpsm  = wsm + K2 * COUT * WSTR;                 // 16*WSTR
    float*  bsm   = (float*)(wpsm + CIN * WSTR);

    const int t = threadIdx.x, lane = t & 31, w = t >> 5;
    for (int i = t; i < K2 * COUT * COUT; i += 256) {
        int row = i >> 5, cc = i & 31;
        wsm[row * WSTR + cc] = g_w2h[i];
    }
    for (int i = t; i < CIN * COUT; i += 256) {
        int row = i >> 5, cc = i & 31;
        wpsm[row * WSTR + cc] = g_wph[i];
    }
    if (t < COUT) bsm[t] = __ldg(b2 + t) + __ldg(bp + t);
    __syncthreads();

    const int grp = lane >> 2, tig = lane & 3;
    const int sub = lane & 7, ti = lane >> 3;
    const int v0w = blockIdx.x * (8 * M2) + w * M2;
    const int prow = lane >> 1;      // pair-coop: row within 16-row segment
    const int phalf = lane & 1;      // 32B half of the 64B row

    char* atw = (char*)atile + w * M2 * AROW;
    const unsigned abase = (unsigned)__cvta_generic_to_shared(atw);
    const unsigned wb0 = (unsigned)__cvta_generic_to_shared(wsm);
    const unsigned wpb = (unsigned)__cvta_generic_to_shared(wpsm);
    const int lro = sub + ((ti & 1) << 3);
    const int lco = (ti >> 1) << 4;

    float acc[3][4][4];
#pragma unroll
    for (int m = 0; m < 3; m++)
#pragma unroll
        for (int nt = 0; nt < 4; nt++) {
            float c0 = bsm[8 * nt + 2 * tig], c1 = bsm[8 * nt + 2 * tig + 1];
            acc[m][nt][0] = c0; acc[m][nt][1] = c1;
            acc[m][nt][2] = c0; acc[m][nt][3] = c1;
        }

    // depth-2 staging: 2 sets x 3 segments x 32B
    uint4 s[2][3][2];
    int inx[3];   // cidx for the tap whose rows load next

    auto load_idx = [&](int k) {
#pragma unroll
        for (int seg = 0; seg < 3; seg++) {
            int vx = v0w + seg * 16 + prow;
            inx[seg] = (vx < n) ? __ldg(g_cidx + (size_t)k * n + vx) : -1;
        }
    };
    auto load_rows = [&](int set) {
#pragma unroll
        for (int seg = 0; seg < 3; seg++) {
            int c = inx[seg];
            const char* p = (c >= 0) ? (const char*)(g_h1h + (size_t)c * COUT)
                                     : (const char*)g_zrow;
            ldg256(p + phalf * 32, s[set][seg][0], s[set][seg][1]);
        }
    };
    auto sts_rows = [&](int set) {
#pragma unroll
        for (int seg = 0; seg < 3; seg++) {
            char* d = atw + (seg * 16 + prow) * AROW + phalf * 32;
            ((uint4*)d)[0] = s[set][seg][0];
            ((uint4*)d)[1] = s[set][seg][1];
        }
    };

    // ---- stage proj rows (own x, coalesced): rows 0..31 by lane, 32..47 pair-coop
    {
        uint4 p0, p1;
        int v = v0w + lane;
        if (v < n) ldg256(g_xh + (size_t)v * CIN, p0, p1);
        else { p0 = make_uint4(0, 0, 0, 0); p1 = p0; }
        char* d = atw + lane * AROW;
        ((uint4*)d)[0] = p0; ((uint4*)d)[1] = p1;
        int v2 = v0w + 32 + prow;            // rows 32..47, 2 lanes x 16B
        uint4 q;
        if (v2 < n) {
            const uint4* src = (const uint4*)(g_xh + (size_t)v2 * CIN) + phalf;
            q = __ldg(src);
        } else q = make_uint4(0, 0, 0, 0);
        char* d2 = atw + (32 + prow) * AROW + phalf * 16;
        *(uint4*)d2 = q;
        __syncwarp();
    }

    // pipeline start: rows(0)->set0, rows(1)->set1 (overlap proj MMA)
    load_idx(0); load_rows(0);
    load_idx(1); load_rows(1);
    load_idx(2);

    // proj MMA (K=16)
    {
        unsigned bw[8];
        unsigned wp0 = wpb + lro * (WSTR * 2) + lco;
        ldsm4t(bw,     wp0);
        ldsm4t(bw + 4, wp0 + 32);
#pragma unroll
        for (int m = 0; m < 3; m++) {
            unsigned av[4];
            ldsm4(av, abase + (16 * m + lro) * AROW + lco);
            mma16816(acc[m][0], av, bw[0], bw[1]);
            mma16816(acc[m][1], av, bw[2], bw[3]);
            mma16816(acc[m][2], av, bw[4], bw[5]);
            mma16816(acc[m][3], av, bw[6], bw[7]);
        }
        __syncwarp();
    }

    // ---- 9 conv taps (K=32) ----
#pragma unroll
    for (int k = 0; k < K2; k++) {
        sts_rows(k & 1);
        __syncwarp();
        if (k + 2 < K2) { load_rows(k & 1); }   // idx(k+2) already in inx
        if (k + 3 < K2) load_idx(k + 3);
        unsigned wtap = wb0 + k * (COUT * WSTR * 2);
#pragma unroll
        for (int kt = 0; kt < 2; kt++) {
            unsigned bw[8];
            unsigned wk = wtap + (16 * kt + lro) * (WSTR * 2) + lco;
            ldsm4t(bw,     wk);
            ldsm4t(bw + 4, wk + 32);
#pragma unroll
            for (int m = 0; m < 3; m++) {
                unsigned av[4];
                ldsm4(av, abase + (16 * m + lro) * AROW + kt * 32 + lco);
                mma16816(acc[m][0], av, bw[0], bw[1]);
                mma16816(acc[m][1], av, bw[2], bw[3]);
                mma16816(acc[m][2], av, bw[4], bw[5]);
                mma16816(acc[m][3], av, bw[6], bw[7]);
            }
        }
        __syncwarp();
    }

    // epilogue: relu -> fp32 out
#pragma unroll
    for (int m = 0; m < 3; m++) {
        int vg0 = v0w + 16 * m + grp, vg1 = vg0 + 8;
#pragma unroll
        for (int nt = 0; nt < 4; nt++) {
            const float* a = acc[m][nt];
            if (vg0 < n)
                *(float2*)(out + (size_t)vg0 * COUT + 8 * nt + 2 * tig) =
                    make_float2(fmaxf(a[0], 0.f), fmaxf(a[1], 0.f));
            if (vg1 < n)
                *(float2*)(out + (size_t)vg1 * COUT + 8 * nt + 2 * tig) =
                    make_float2(fmaxf(a[2], 0.f), fmaxf(a[3], 0.f));
        }
    }
}

// =====================================================================
// Launch.  Input order: x, W1, b1, W2, b2, Wp, bp, nbr_idx, nbr_mask
// =====================================================================
extern "C" void kernel_launch(void* const* d_in, const int* in_sizes, int n_in,
                              void* d_out, int out_size) {
    const float* x  = (const float*)d_in[0];
    const float* W1 = (const float*)d_in[1];
    const float* b1 = (const float*)d_in[2];
    const float* W2 = (const float*)d_in[3];
    const float* b2 = (const float*)d_in[4];
    const float* Wp = (const float*)d_in[5];
    const float* bp = (const float*)d_in[6];
    const int* nbr_idx = (const int*)d_in[7];
    const unsigned* nbr_mask = (const unsigned*)d_in[8];
    float* out = (float*)d_out;

    int n = in_sizes[0] / CIN;
    if (n > MAXN) n = MAXN;

    const int smem2 = 8 * M2 * AROW + K2 * COUT * WSTR * 2 + CIN * WSTR * 2 + COUT * 4;
    cudaFuncSetAttribute(conv2_kernel, cudaFuncAttributeMaxDynamicSharedMemorySize, smem2);

    xhw_kernel<<<512, 256>>>(x, W1, W2, Wp, n);

    int blocks1 = (n + 511) / 512;
    conv1_kernel<<<blocks1, 256>>>(nbr_idx, nbr_mask, b1, n);
    int blocks2 = (n + 8 * M2 - 1) / (8 * M2);
    conv2_kernel<<<blocks2, 256, smem2>>>(b2, bp, out, n);
}